// round 1
// baseline (speedup 1.0000x reference)
#include <cuda_runtime.h>
#include <math.h>

// Problem shape (fixed by the reference)
#define B_DIM 2048
#define D_DIM 512
#define C_DIM 32000
#define SCALE_F 32.0f
#define MARGIN_F 16.0f   // M * SCALE = 0.5 * 32

// Scratch: per-row inverse norms (device globals; no allocation allowed)
__device__ float g_invnx[B_DIM];
__device__ float g_invnw[C_DIM];

// ---------------------------------------------------------------------------
// Row inverse-norm: one block per row, 128 threads, one float4 each (D=512).
// which==0 -> g_invnx, which==1 -> g_invnw
// ---------------------------------------------------------------------------
__global__ void rownorm_kernel(const float* __restrict__ v, int which) {
    int row = blockIdx.x;
    const float4* p = reinterpret_cast<const float4*>(v + (size_t)row * D_DIM);
    float4 t = p[threadIdx.x];
    float s = t.x * t.x + t.y * t.y + t.z * t.z + t.w * t.w;
    #pragma unroll
    for (int o = 16; o > 0; o >>= 1)
        s += __shfl_down_sync(0xffffffffu, s, o);
    __shared__ float ws[4];
    int lane = threadIdx.x & 31;
    int w = threadIdx.x >> 5;
    if (lane == 0) ws[w] = s;
    __syncthreads();
    if (threadIdx.x == 0) {
        float tot = ws[0] + ws[1] + ws[2] + ws[3];
        float inv = 1.0f / fmaxf(sqrtf(tot), 1e-12f);
        if (which == 0) g_invnx[row] = inv;
        else            g_invnw[row] = inv;
    }
}

// ---------------------------------------------------------------------------
// SGEMM: O[b,c] = dot(X[b,:], W[c,:]) * invnx[b] * invnw[c] * 32
// Tiles: BM=128, BN=128, BK=8. 256 threads, 8x8 micro-tile per thread.
// Writes both out_loss and out_pred (identical; margin applied after).
// All dims divide evenly (2048/128, 32000/128, 512/8) -> no bounds checks.
// ---------------------------------------------------------------------------
__launch_bounds__(256)
__global__ void cosgemm_kernel(const float* __restrict__ X,
                               const float* __restrict__ W,
                               float* __restrict__ out_loss,
                               float* __restrict__ out_pred) {
    __shared__ float As[8][128];
    __shared__ float Bs[8][128];

    const int tid = threadIdx.x;
    const int tx = tid & 15;      // 0..15 -> N micro
    const int ty = tid >> 4;      // 0..15 -> M micro
    const int lrow = tid >> 1;    // 0..127: row loaded by this thread
    const int lcol = (tid & 1) * 4;

    const float* xg = X + (size_t)((size_t)blockIdx.y * 128 + lrow) * D_DIM + lcol;
    const float* wg = W + (size_t)((size_t)blockIdx.x * 128 + lrow) * D_DIM + lcol;

    float acc[8][8];
    #pragma unroll
    for (int i = 0; i < 8; i++)
        #pragma unroll
        for (int j = 0; j < 8; j++)
            acc[i][j] = 0.0f;

    for (int k0 = 0; k0 < D_DIM; k0 += 8) {
        float4 a = *reinterpret_cast<const float4*>(xg + k0);
        float4 b = *reinterpret_cast<const float4*>(wg + k0);
        __syncthreads();
        As[lcol + 0][lrow] = a.x;
        As[lcol + 1][lrow] = a.y;
        As[lcol + 2][lrow] = a.z;
        As[lcol + 3][lrow] = a.w;
        Bs[lcol + 0][lrow] = b.x;
        Bs[lcol + 1][lrow] = b.y;
        Bs[lcol + 2][lrow] = b.z;
        Bs[lcol + 3][lrow] = b.w;
        __syncthreads();

        #pragma unroll
        for (int k = 0; k < 8; k++) {
            float4 a0 = *reinterpret_cast<const float4*>(&As[k][ty * 8]);
            float4 a1 = *reinterpret_cast<const float4*>(&As[k][ty * 8 + 4]);
            float4 b0 = *reinterpret_cast<const float4*>(&Bs[k][tx * 8]);
            float4 b1 = *reinterpret_cast<const float4*>(&Bs[k][tx * 8 + 4]);
            float ra[8] = {a0.x, a0.y, a0.z, a0.w, a1.x, a1.y, a1.z, a1.w};
            float rb[8] = {b0.x, b0.y, b0.z, b0.w, b1.x, b1.y, b1.z, b1.w};
            #pragma unroll
            for (int i = 0; i < 8; i++)
                #pragma unroll
                for (int j = 0; j < 8; j++)
                    acc[i][j] = fmaf(ra[i], rb[j], acc[i][j]);
        }
    }

    // Epilogue: fold normalization + scale, write both outputs.
    const int row0 = blockIdx.y * 128 + ty * 8;
    const int col0 = blockIdx.x * 128 + tx * 8;
    float sw[8];
    #pragma unroll
    for (int j = 0; j < 8; j++) sw[j] = g_invnw[col0 + j];

    #pragma unroll
    for (int i = 0; i < 8; i++) {
        float sx = g_invnx[row0 + i] * SCALE_F;
        float4 v0, v1;
        v0.x = acc[i][0] * sx * sw[0];
        v0.y = acc[i][1] * sx * sw[1];
        v0.z = acc[i][2] * sx * sw[2];
        v0.w = acc[i][3] * sx * sw[3];
        v1.x = acc[i][4] * sx * sw[4];
        v1.y = acc[i][5] * sx * sw[5];
        v1.z = acc[i][6] * sx * sw[6];
        v1.w = acc[i][7] * sx * sw[7];
        size_t off = (size_t)(row0 + i) * C_DIM + col0;
        *reinterpret_cast<float4*>(out_pred + off)     = v0;
        *reinterpret_cast<float4*>(out_pred + off + 4) = v1;
        *reinterpret_cast<float4*>(out_loss + off)     = v0;
        *reinterpret_cast<float4*>(out_loss + off + 4) = v1;
    }
}

// ---------------------------------------------------------------------------
// Margin scatter. Targets may arrive as int32 or int64 (jax emits int64).
// Probe within the first 2048 int32 words (safe under both layouts):
// if ALL odd words are zero -> int64 little-endian (values < 32000, high=0).
// Probability of false positive with real int32 targets: (1/32000)^1024 ~ 0.
// ---------------------------------------------------------------------------
__global__ void margin_kernel(const void* __restrict__ targets,
                              float* __restrict__ out_loss) {
    const int tid = threadIdx.x;  // 1024 threads, one block
    const int* ti = reinterpret_cast<const int*>(targets);
    int odd = ti[2 * tid + 1];
    int any_nonzero = __syncthreads_or(odd != 0);
    const bool is64 = (any_nonzero == 0);

    #pragma unroll
    for (int r = 0; r < 2; r++) {
        int b = tid + r * 1024;
        long long t;
        if (is64) t = reinterpret_cast<const long long*>(targets)[b];
        else      t = (long long)ti[b];
        out_loss[(size_t)b * C_DIM + (size_t)t] -= MARGIN_F;
    }
}

// ---------------------------------------------------------------------------
extern "C" void kernel_launch(void* const* d_in, const int* in_sizes, int n_in,
                              void* d_out, int out_size) {
    const float* x = (const float*)d_in[0];   // [2048, 512]
    const float* w = (const float*)d_in[1];   // [32000, 512]
    const void*  tg = d_in[2];                // [2048] int32 or int64

    float* out_loss = (float*)d_out;                          // first tuple element
    float* out_pred = out_loss + (size_t)B_DIM * C_DIM;       // second tuple element

    rownorm_kernel<<<B_DIM, 128>>>(x, 0);
    rownorm_kernel<<<C_DIM, 128>>>(w, 1);

    dim3 grid(C_DIM / 128, B_DIM / 128);  // (250, 16)
    cosgemm_kernel<<<grid, 256>>>(x, w, out_loss, out_pred);

    margin_kernel<<<1, 1024>>>(tg, out_loss);
}

// round 3
// speedup vs baseline: 2.4273x; 2.4273x over previous
#include <cuda_runtime.h>
#include <cuda_bf16.h>
#include <math.h>
#include <stdint.h>

#define B_DIM 2048
#define D_DIM 512
#define C_DIM 32000
#define SCALE_F 32.0f
#define MARGIN_F 16.0f

// ---------------- scratch (device globals; no allocation allowed) ----------
__device__ float g_invnx[B_DIM];
__device__ float g_invnw[C_DIM];
__device__ __align__(16) __nv_bfloat16 g_xhi[(size_t)B_DIM * D_DIM];
__device__ __align__(16) __nv_bfloat16 g_xlo[(size_t)B_DIM * D_DIM];
__device__ __align__(16) __nv_bfloat16 g_whi[(size_t)C_DIM * D_DIM];
__device__ __align__(16) __nv_bfloat16 g_wlo[(size_t)C_DIM * D_DIM];

// ---------------- helpers ----------------------------------------------------
static __device__ __forceinline__ uint32_t smem_u32(const void* p) {
    uint32_t a;
    asm("{ .reg .u64 t; cvta.to.shared.u64 t, %1; cvt.u32.u64 %0, t; }" : "=r"(a) : "l"(p));
    return a;
}
static __device__ __forceinline__ void cp16(uint32_t dst, const void* src) {
    asm volatile("cp.async.cg.shared.global [%0], [%1], 16;" :: "r"(dst), "l"(src));
}
static __device__ __forceinline__ void ldsm_x4(uint32_t* r, uint32_t addr) {
    asm volatile("ldmatrix.sync.aligned.m8n8.x4.shared.b16 {%0,%1,%2,%3}, [%4];"
                 : "=r"(r[0]), "=r"(r[1]), "=r"(r[2]), "=r"(r[3]) : "r"(addr));
}
static __device__ __forceinline__ void mma_bf16(float* d, const uint32_t* a,
                                                uint32_t b0, uint32_t b1) {
    asm volatile(
        "mma.sync.aligned.m16n8k16.row.col.f32.bf16.bf16.f32 "
        "{%0,%1,%2,%3}, {%4,%5,%6,%7}, {%8,%9}, {%0,%1,%2,%3};"
        : "+f"(d[0]), "+f"(d[1]), "+f"(d[2]), "+f"(d[3])
        : "r"(a[0]), "r"(a[1]), "r"(a[2]), "r"(a[3]), "r"(b0), "r"(b1));
}

// ---------------- row inverse-norms ------------------------------------------
__global__ void rownorm_kernel(const float* __restrict__ v, int which) {
    int row = blockIdx.x;
    const float4* p = reinterpret_cast<const float4*>(v + (size_t)row * D_DIM);
    float4 t = p[threadIdx.x];
    float s = t.x * t.x + t.y * t.y + t.z * t.z + t.w * t.w;
    #pragma unroll
    for (int o = 16; o > 0; o >>= 1) s += __shfl_down_sync(0xffffffffu, s, o);
    __shared__ float ws[4];
    int lane = threadIdx.x & 31, w = threadIdx.x >> 5;
    if (lane == 0) ws[w] = s;
    __syncthreads();
    if (threadIdx.x == 0) {
        float inv = 1.0f / fmaxf(sqrtf(ws[0] + ws[1] + ws[2] + ws[3]), 1e-12f);
        if (which == 0) g_invnx[row] = inv;
        else            g_invnw[row] = inv;
    }
}

// ---------------- converter: f32 -> bf16 hi/lo (row-major) -------------------
__global__ void convert_kernel(const float* __restrict__ src,
                               __nv_bfloat16* __restrict__ hi,
                               __nv_bfloat16* __restrict__ lo) {
    size_t idx = (size_t)blockIdx.x * blockDim.x + threadIdx.x;  // quad index
    float4 v = reinterpret_cast<const float4*>(src)[idx];
    float f[4] = {v.x, v.y, v.z, v.w};
    __nv_bfloat16 h[4], l[4];
    #pragma unroll
    for (int i = 0; i < 4; i++) {
        h[i] = __float2bfloat16_rn(f[i]);
        l[i] = __float2bfloat16_rn(f[i] - __bfloat162float(h[i]));
    }
    *reinterpret_cast<uint2*>(hi + idx * 4) =
        make_uint2(*(uint32_t*)&h[0] | ((uint32_t)*(uint16_t*)&h[1] << 16),
                   *(uint32_t*)&h[2] | ((uint32_t)*(uint16_t*)&h[3] << 16));
    *reinterpret_cast<uint2*>(lo + idx * 4) =
        make_uint2(*(uint32_t*)&l[0] | ((uint32_t)*(uint16_t*)&l[1] << 16),
                   *(uint32_t*)&l[2] | ((uint32_t)*(uint16_t*)&l[3] << 16));
}

// ---------------- GEMM: bf16 mma.sync, 3-product compensated ----------------
// CTA tile 128(m) x 256(n), BK = 64 halves (128B rows). 512 threads, 16 warps
// (warp grid 4m x 4n, warp tile m32 x n64). 2-stage cp.async pipeline.
// smem: [0..512) invnx, [512..1536) invnw, [2048 + s*98304): stage s
//   stage: Ahi 16KB | Alo 16KB | Bhi 32KB | Blo 32KB   (row = 128B, swizzled)
#define STAGE_B 98304u
#define SMEM_TOTAL (2048u + 2u * STAGE_B)

static __device__ __forceinline__ uint32_t swz(uint32_t row, uint32_t quad) {
    return row * 128u + ((quad ^ (row & 7u)) << 4);
}

__global__ void __launch_bounds__(512, 1)
gemm_kernel(float* __restrict__ out_loss, float* __restrict__ out_pred) {
    extern __shared__ __align__(128) unsigned char smem[];
    const uint32_t sb = smem_u32(smem);
    const uint32_t st0 = sb + 2048u;
    const int tid = threadIdx.x;
    const int wid = tid >> 5, lane = tid & 31;
    const int wm = wid & 3, wn = wid >> 2;

    const int bid = blockIdx.x;          // 0..1999, m-fastest for L2 reuse of W
    const int mt = bid & 15, nt = bid >> 4;
    const int m0 = mt * 128, n0 = nt * 256;

    float* s_nx = reinterpret_cast<float*>(smem);
    float* s_nw = reinterpret_cast<float*>(smem + 512);
    if (tid < 128) s_nx[tid] = g_invnx[m0 + tid];
    if (tid < 256) s_nw[tid] = g_invnw[n0 + tid];

    // ---- g2s issue for one K-chunk (64 halves) into stage s ----
    auto issue = [&](int s, int chunk) {
        uint32_t st = st0 + (uint32_t)s * STAGE_B;
        int k0 = chunk * 64;
        #pragma unroll
        for (int i = 0; i < 2; i++) {          // A: 1024 chunks of 16B
            int idx = tid + i * 512;
            uint32_t row = idx >> 3, q = idx & 7;
            uint32_t d = st + swz(row, q);
            size_t goff = ((size_t)(m0 + row) * D_DIM + k0 + q * 8);
            cp16(d,          g_xhi + goff);
            cp16(d + 16384u, g_xlo + goff);
        }
        #pragma unroll
        for (int i = 0; i < 4; i++) {          // B: 2048 chunks of 16B
            int idx = tid + i * 512;
            uint32_t row = idx >> 3, q = idx & 7;
            uint32_t d = st + 32768u + swz(row, q);
            size_t goff = ((size_t)(n0 + row) * D_DIM + k0 + q * 8);
            cp16(d,          g_whi + goff);
            cp16(d + 32768u, g_wlo + goff);
        }
        asm volatile("cp.async.commit_group;" ::: "memory");
    };

    float acc[2][8][4];
    #pragma unroll
    for (int i = 0; i < 2; i++)
        #pragma unroll
        for (int j = 0; j < 8; j++)
            #pragma unroll
            for (int q = 0; q < 4; q++) acc[i][j][q] = 0.0f;

    issue(0, 0);
    issue(1, 1);

    const uint32_t arow = lane & 15;      // ldmatrix row within 16
    const uint32_t akq  = lane >> 4;      // ldmatrix k-quad select (0/1)

    #pragma unroll 1
    for (int c = 0; c < 8; c++) {         // 8 K-chunks of 64
        if (c < 6) asm volatile("cp.async.wait_group 1;" ::: "memory");
        else       asm volatile("cp.async.wait_group 0;" ::: "memory");
        __syncthreads();

        uint32_t st = st0 + (uint32_t)(c & 1) * STAGE_B;
        #pragma unroll
        for (int s = 0; s < 4; s++) {     // 4 k16 steps
            uint32_t qb = 2 * s + akq;
            uint32_t ah[2][4], al[2][4], bh[4][4], bl[4][4];
            #pragma unroll
            for (int mi = 0; mi < 2; mi++) {
                uint32_t row = (uint32_t)(wm * 32 + mi * 16) + arow;
                uint32_t a = st + swz(row, qb);
                ldsm_x4(ah[mi], a);
                ldsm_x4(al[mi], a + 16384u);
            }
            #pragma unroll
            for (int ni = 0; ni < 4; ni++) {
                uint32_t row = (uint32_t)(wn * 64 + ni * 16) + arow;
                uint32_t b = st + 32768u + swz(row, qb);
                ldsm_x4(bh[ni], b);
                ldsm_x4(bl[ni], b + 32768u);
            }
            #pragma unroll
            for (int mi = 0; mi < 2; mi++)
                #pragma unroll
                for (int nb = 0; nb < 8; nb++) {
                    int ni = nb >> 1, sel = nb & 1;
                    mma_bf16(acc[mi][nb], ah[mi], bh[ni][0 + sel], bh[ni][2 + sel]);
                    mma_bf16(acc[mi][nb], ah[mi], bl[ni][0 + sel], bl[ni][2 + sel]);
                    mma_bf16(acc[mi][nb], al[mi], bh[ni][0 + sel], bh[ni][2 + sel]);
                }
        }
        __syncthreads();
        if (c + 2 < 8) issue(c & 1, c + 2);
    }

    // ---- epilogue: fold invnx*invnw*SCALE, write both outputs ----
    const int gr = lane >> 2, gc = lane & 3;
    #pragma unroll
    for (int mi = 0; mi < 2; mi++) {
        int rl = wm * 32 + mi * 16 + gr;
        float sx0 = s_nx[rl] * SCALE_F;
        float sx1 = s_nx[rl + 8] * SCALE_F;
        size_t off0 = (size_t)(m0 + rl) * C_DIM + n0;
        size_t off1 = off0 + (size_t)8 * C_DIM;
        #pragma unroll
        for (int nb = 0; nb < 8; nb++) {
            int col = wn * 64 + nb * 8 + gc * 2;
            float sw0 = s_nw[col], sw1 = s_nw[col + 1];
            float2 v0 = make_float2(acc[mi][nb][0] * sx0 * sw0,
                                    acc[mi][nb][1] * sx0 * sw1);
            float2 v1 = make_float2(acc[mi][nb][2] * sx1 * sw0,
                                    acc[mi][nb][3] * sx1 * sw1);
            *reinterpret_cast<float2*>(out_pred + off0 + col) = v0;
            *reinterpret_cast<float2*>(out_pred + off1 + col) = v1;
            *reinterpret_cast<float2*>(out_loss + off0 + col) = v0;
            *reinterpret_cast<float2*>(out_loss + off1 + col) = v1;
        }
    }
}

// ---------------- margin scatter (int32/int64 targets probe) ----------------
__global__ void margin_kernel(const void* __restrict__ targets,
                              float* __restrict__ out_loss) {
    const int tid = threadIdx.x;  // 1024 threads, one block
    const int* ti = reinterpret_cast<const int*>(targets);
    int odd = ti[2 * tid + 1];
    int any_nonzero = __syncthreads_or(odd != 0);
    const bool is64 = (any_nonzero == 0);
    #pragma unroll
    for (int r = 0; r < 2; r++) {
        int b = tid + r * 1024;
        long long t;
        if (is64) t = reinterpret_cast<const long long*>(targets)[b];
        else      t = (long long)ti[b];
        out_loss[(size_t)b * C_DIM + (size_t)t] -= MARGIN_F;
    }
}

// ---------------------------------------------------------------------------
extern "C" void kernel_launch(void* const* d_in, const int* in_sizes, int n_in,
                              void* d_out, int out_size) {
    const float* x  = (const float*)d_in[0];
    const float* w  = (const float*)d_in[1];
    const void*  tg = d_in[2];

    float* out_loss = (float*)d_out;
    float* out_pred = out_loss + (size_t)B_DIM * C_DIM;

    rownorm_kernel<<<B_DIM, 128>>>(x, 0);
    rownorm_kernel<<<C_DIM, 128>>>(w, 1);

    __nv_bfloat16 *xhi, *xlo, *whi, *wlo;
    cudaGetSymbolAddress((void**)&xhi, g_xhi);
    cudaGetSymbolAddress((void**)&xlo, g_xlo);
    cudaGetSymbolAddress((void**)&whi, g_whi);
    cudaGetSymbolAddress((void**)&wlo, g_wlo);
    convert_kernel<<<(B_DIM * D_DIM / 4) / 256, 256>>>(x, xhi, xlo);
    convert_kernel<<<(C_DIM * D_DIM / 4) / 256, 256>>>(w, whi, wlo);

    static int smem_set = 0;
    if (!smem_set) {
        cudaFuncSetAttribute(gemm_kernel, cudaFuncAttributeMaxDynamicSharedMemorySize, SMEM_TOTAL);
        smem_set = 1;
    }
    gemm_kernel<<<2000, 512, SMEM_TOTAL>>>(out_loss, out_pred);

    margin_kernel<<<1, 1024>>>(tg, out_loss);
}

// round 6
// speedup vs baseline: 2.5196x; 1.0380x over previous
#include <cuda_runtime.h>
#include <cuda_bf16.h>
#include <math.h>
#include <stdint.h>

#define B_DIM 2048
#define D_DIM 512
#define C_DIM 32000
#define SCALE_F 32.0f
#define MARGIN_F 16.0f

// ---------------- scratch (device globals; no allocation allowed) ----------
__device__ float g_invnx[B_DIM];
__device__ float g_invnw[C_DIM];
__device__ int   g_tgt[B_DIM];
__device__ __align__(16) __nv_bfloat16 g_xhi[(size_t)B_DIM * D_DIM];
__device__ __align__(16) __nv_bfloat16 g_xlo[(size_t)B_DIM * D_DIM];
__device__ __align__(16) __nv_bfloat16 g_whi[(size_t)C_DIM * D_DIM];
__device__ __align__(16) __nv_bfloat16 g_wlo[(size_t)C_DIM * D_DIM];

// ---------------- helpers ----------------------------------------------------
static __device__ __forceinline__ uint32_t smem_u32(const void* p) {
    uint32_t a;
    asm("{ .reg .u64 t; cvta.to.shared.u64 t, %1; cvt.u32.u64 %0, t; }" : "=r"(a) : "l"(p));
    return a;
}
static __device__ __forceinline__ void cp16(uint32_t dst, const void* src) {
    asm volatile("cp.async.cg.shared.global [%0], [%1], 16;" :: "r"(dst), "l"(src) : "memory");
}
static __device__ __forceinline__ void ldsm_x4(uint32_t* r, uint32_t addr) {
    asm volatile("ldmatrix.sync.aligned.m8n8.x4.shared.b16 {%0,%1,%2,%3}, [%4];"
                 : "=r"(r[0]), "=r"(r[1]), "=r"(r[2]), "=r"(r[3]) : "r"(addr));
}
static __device__ __forceinline__ void mma_bf16(float* d, const uint32_t* a,
                                                uint32_t b0, uint32_t b1) {
    asm volatile(
        "mma.sync.aligned.m16n8k16.row.col.f32.bf16.bf16.f32 "
        "{%0,%1,%2,%3}, {%4,%5,%6,%7}, {%8,%9}, {%0,%1,%2,%3};"
        : "+f"(d[0]), "+f"(d[1]), "+f"(d[2]), "+f"(d[3])
        : "r"(a[0]), "r"(a[1]), "r"(a[2]), "r"(a[3]), "r"(b0), "r"(b1));
}

// ---------------- fused rownorm + bf16 hi/lo convert -------------------------
__global__ void prep_kernel(const float* __restrict__ src,
                            float* __restrict__ invn,
                            __nv_bfloat16* __restrict__ hi,
                            __nv_bfloat16* __restrict__ lo) {
    int row = blockIdx.x;
    size_t base = (size_t)row * D_DIM + threadIdx.x * 4;
    float4 v = *reinterpret_cast<const float4*>(src + base);

    float s = v.x * v.x + v.y * v.y + v.z * v.z + v.w * v.w;
    #pragma unroll
    for (int o = 16; o > 0; o >>= 1) s += __shfl_down_sync(0xffffffffu, s, o);
    __shared__ float ws[4];
    int lane = threadIdx.x & 31, w = threadIdx.x >> 5;
    if (lane == 0) ws[w] = s;

    float f[4] = {v.x, v.y, v.z, v.w};
    __nv_bfloat16 h[4], l[4];
    #pragma unroll
    for (int i = 0; i < 4; i++) {
        h[i] = __float2bfloat16_rn(f[i]);
        l[i] = __float2bfloat16_rn(f[i] - __bfloat162float(h[i]));
    }
    *reinterpret_cast<uint2*>(hi + base) =
        make_uint2(*(uint32_t*)&h[0] | ((uint32_t)*(uint16_t*)&h[1] << 16),
                   *(uint32_t*)&h[2] | ((uint32_t)*(uint16_t*)&h[3] << 16));
    *reinterpret_cast<uint2*>(lo + base) =
        make_uint2(*(uint32_t*)&l[0] | ((uint32_t)*(uint16_t*)&l[1] << 16),
                   *(uint32_t*)&l[2] | ((uint32_t)*(uint16_t*)&l[3] << 16));

    __syncthreads();
    if (threadIdx.x == 0)
        invn[row] = 1.0f / fmaxf(sqrtf(ws[0] + ws[1] + ws[2] + ws[3]), 1e-12f);
}

// ---------------- decode targets (R3-proven global probe) -------------------
__global__ void decode_targets(const void* __restrict__ targets,
                               int* __restrict__ tgt) {
    const int tid = threadIdx.x;  // one block, 1024 threads
    const int* ti = reinterpret_cast<const int*>(targets);
    int odd = ti[2 * tid + 1];
    int any_nonzero = __syncthreads_or(odd != 0);
    const bool is64 = (any_nonzero == 0);
    #pragma unroll
    for (int r = 0; r < 2; r++) {
        int b = tid + r * 1024;
        int t;
        if (is64) t = (int)reinterpret_cast<const long long*>(targets)[b];
        else      t = ti[b];
        tgt[b] = t;
    }
}

// ---------------- GEMM: bf16 mma.sync, 3-product compensated ----------------
// CTA tile 128(m) x 256(n), BK = 64. 256 threads, 8 warps (2m x 4n),
// warp tile m64 x n64. 2-stage cp.async pipeline, 96KB/stage.
// smem: [0..512) invnx, [512..1536) invnw, [1536..2048) targets(int),
//       [2048 + s*98304): stage s = Ahi 16K | Alo 16K | Bhi 32K | Blo 32K
#define STAGE_B 98304u
#define SMEM_TOTAL (2048u + 2u * STAGE_B)

static __device__ __forceinline__ uint32_t swz(uint32_t row, uint32_t quad) {
    return row * 128u + ((quad ^ (row & 7u)) << 4);
}

__global__ void __launch_bounds__(256, 1)
gemm_kernel(float* __restrict__ out_loss, float* __restrict__ out_pred) {
    extern __shared__ __align__(128) unsigned char smem[];
    const uint32_t sb = smem_u32(smem);
    const uint32_t st0 = sb + 2048u;
    const int tid = threadIdx.x;
    const int wid = tid >> 5, lane = tid & 31;
    const int wm = wid & 1, wn = wid >> 1;

    const int bid = blockIdx.x;          // m-fastest: consecutive CTAs share W panel
    const int mt = bid & 15, nt = bid >> 4;
    const int m0 = mt * 128, n0 = nt * 256;

    float* s_nx = reinterpret_cast<float*>(smem);
    float* s_nw = reinterpret_cast<float*>(smem + 512);
    int*   s_tg = reinterpret_cast<int*>(smem + 1536);
    if (tid < 128) {
        s_nx[tid] = g_invnx[m0 + tid];
        s_tg[tid] = g_tgt[m0 + tid] - n0;   // relative column of margin target
    }
    s_nw[tid] = g_invnw[n0 + tid];
    __syncthreads();

    // ---- g2s issue for one K-chunk (64 halves = 128B rows) into stage s ----
    auto issue = [&](int s, int chunk) {
        uint32_t st = st0 + (uint32_t)s * STAGE_B;
        int k0 = chunk * 64;
        #pragma unroll
        for (int i = 0; i < 4; i++) {          // A: 1024 cp16 per buffer
            int idx = tid + i * 256;
            uint32_t row = (uint32_t)idx >> 3, q = (uint32_t)idx & 7;
            uint32_t d = st + swz(row, q);
            size_t goff = ((size_t)(m0 + row) * D_DIM + k0 + q * 8);
            cp16(d,          g_xhi + goff);
            cp16(d + 16384u, g_xlo + goff);
        }
        #pragma unroll
        for (int i = 0; i < 8; i++) {          // B: 2048 cp16 per buffer
            int idx = tid + i * 256;
            uint32_t row = (uint32_t)idx >> 3, q = (uint32_t)idx & 7;
            uint32_t d = st + 32768u + swz(row, q);
            size_t goff = ((size_t)(n0 + row) * D_DIM + k0 + q * 8);
            cp16(d,          g_whi + goff);
            cp16(d + 32768u, g_wlo + goff);
        }
        asm volatile("cp.async.commit_group;" ::: "memory");
    };

    float acc[4][8][4];
    #pragma unroll
    for (int i = 0; i < 4; i++)
        #pragma unroll
        for (int j = 0; j < 8; j++)
            #pragma unroll
            for (int q = 0; q < 4; q++) acc[i][j][q] = 0.0f;

    issue(0, 0);
    issue(1, 1);

    const uint32_t arow = lane & 15;      // ldmatrix row within 16
    const uint32_t akq  = lane >> 4;      // k-quad select (0/1)

    #pragma unroll 1
    for (int c = 0; c < 8; c++) {
        if (c < 6) asm volatile("cp.async.wait_group 1;" ::: "memory");
        else       asm volatile("cp.async.wait_group 0;" ::: "memory");
        __syncthreads();

        uint32_t st = st0 + (uint32_t)(c & 1) * STAGE_B;
        #pragma unroll
        for (int s = 0; s < 4; s++) {     // 4 k16 steps, fully unrolled
            uint32_t qb = 2 * s + akq;
            uint32_t ah[4][4], al[4][4], bh[4][4], bl[4][4];
            #pragma unroll
            for (int mi = 0; mi < 4; mi++) {
                uint32_t row = (uint32_t)(wm * 64 + mi * 16) + arow;
                uint32_t a = st + swz(row, qb);
                ldsm_x4(ah[mi], a);
                ldsm_x4(al[mi], a + 16384u);
            }
            #pragma unroll
            for (int ni = 0; ni < 4; ni++) {
                uint32_t row = (uint32_t)(wn * 64 + ni * 16) + arow;
                uint32_t b = st + 32768u + swz(row, qb);
                ldsm_x4(bh[ni], b);
                ldsm_x4(bl[ni], b + 32768u);
            }
            #pragma unroll
            for (int mi = 0; mi < 4; mi++)
                #pragma unroll
                for (int nb = 0; nb < 8; nb++) {
                    int ni = nb >> 1, sel = nb & 1;
                    mma_bf16(acc[mi][nb], ah[mi], bh[ni][0 + sel], bh[ni][2 + sel]);
                    mma_bf16(acc[mi][nb], ah[mi], bl[ni][0 + sel], bl[ni][2 + sel]);
                    mma_bf16(acc[mi][nb], al[mi], bh[ni][0 + sel], bh[ni][2 + sel]);
                }
        }
        __syncthreads();
        if (c + 2 < 8) issue(c & 1, c + 2);
    }

    // ---- epilogue: fold invnx*invnw*SCALE; margin fused into loss stores ----
    const int gr = lane >> 2, gc = lane & 3;
    #pragma unroll
    for (int mi = 0; mi < 4; mi++) {
        int rl = wm * 64 + mi * 16 + gr;      // local row (and rl+8)
        float sx0 = s_nx[rl] * SCALE_F;
        float sx1 = s_nx[rl + 8] * SCALE_F;
        int t0 = s_tg[rl];                    // margin col relative to n0
        int t1 = s_tg[rl + 8];
        size_t off0 = (size_t)(m0 + rl) * C_DIM + n0;
        size_t off1 = off0 + (size_t)8 * C_DIM;
        #pragma unroll
        for (int nb = 0; nb < 8; nb++) {
            int col = wn * 64 + nb * 8 + gc * 2;
            float sw0 = s_nw[col], sw1 = s_nw[col + 1];
            float2 v0 = make_float2(acc[mi][nb][0] * sx0 * sw0,
                                    acc[mi][nb][1] * sx0 * sw1);
            float2 v1 = make_float2(acc[mi][nb][2] * sx1 * sw0,
                                    acc[mi][nb][3] * sx1 * sw1);
            *reinterpret_cast<float2*>(out_pred + off0 + col) = v0;
            *reinterpret_cast<float2*>(out_pred + off1 + col) = v1;
            float2 u0 = v0, u1 = v1;
            if (t0 == col)     u0.x -= MARGIN_F;
            if (t0 == col + 1) u0.y -= MARGIN_F;
            if (t1 == col)     u1.x -= MARGIN_F;
            if (t1 == col + 1) u1.y -= MARGIN_F;
            *reinterpret_cast<float2*>(out_loss + off0 + col) = u0;
            *reinterpret_cast<float2*>(out_loss + off1 + col) = u1;
        }
    }
}

// ---------------------------------------------------------------------------
extern "C" void kernel_launch(void* const* d_in, const int* in_sizes, int n_in,
                              void* d_out, int out_size) {
    const float* x  = (const float*)d_in[0];
    const float* w  = (const float*)d_in[1];
    const void*  tg = d_in[2];

    float* out_loss = (float*)d_out;
    float* out_pred = out_loss + (size_t)B_DIM * C_DIM;

    float *invnx, *invnw;
    int* tgt;
    __nv_bfloat16 *xhi, *xlo, *whi, *wlo;
    cudaGetSymbolAddress((void**)&invnx, g_invnx);
    cudaGetSymbolAddress((void**)&invnw, g_invnw);
    cudaGetSymbolAddress((void**)&tgt,   g_tgt);
    cudaGetSymbolAddress((void**)&xhi, g_xhi);
    cudaGetSymbolAddress((void**)&xlo, g_xlo);
    cudaGetSymbolAddress((void**)&whi, g_whi);
    cudaGetSymbolAddress((void**)&wlo, g_wlo);

    decode_targets<<<1, 1024>>>(tg, tgt);
    prep_kernel<<<B_DIM, 128>>>(x, invnx, xhi, xlo);
    prep_kernel<<<C_DIM, 128>>>(w, invnw, whi, wlo);

    cudaFuncSetAttribute(gemm_kernel, cudaFuncAttributeMaxDynamicSharedMemorySize, SMEM_TOTAL);
    gemm_kernel<<<2000, 256, SMEM_TOTAL>>>(out_loss, out_pred);
}